// round 7
// baseline (speedup 1.0000x reference)
#include <cuda_runtime.h>
#include <math.h>

// ---------------- device scratch (no allocation allowed) ----------------
static __device__ int   g_ntext;
static __device__ int   g_n1;
static __device__ int   g_n0;
static __device__ int   g_list[8192];
static __device__ int   g_ord1[8192];
static __device__ int   g_ord0[8192];
static __device__ float g_ebuf[8192 * 200];
static __device__ float g_vsh[8192 * 20];

// ---------------- kernel 0: zero counters ----------------
__global__ void kzero() { g_ntext = 0; g_n1 = 0; g_n0 = 0; }

// ---------------- kernel 1: partition (text compaction + type buckets) --------
__global__ void kpart(const int* __restrict__ indices,
                      const int* __restrict__ types, int B, int NUv)
{
    int i = blockIdx.x * blockDim.x + threadIdx.x;
    if (i < B) {
        if (indices[i] >= NUv) g_list[atomicAdd(&g_ntext, 1)] = i;
        if (types[i] == 1) g_ord1[atomicAdd(&g_n1, 1)] = i;
        else               g_ord0[atomicAdd(&g_n0, 1)] = i;
    }
}

// ---------------- shared-memory layouts for the combined kernel ----------------
struct GemmS {
    float Xs[2][16][68];
    int   bls[16];
    int   rws[16];
};
struct MainS {
    float xs[4][2][768];   // reused as float4 part[4][24][10] after phase 2
    int   rows[4][20];
    int   bs[4];
    float nte[4][2][20];
    float sc[4][40];
    float att[4][2];
};

// ---------------- kernel 2: combined GEMM + neighbor aggregation ----------------
// Blocks [0, NG):        gathered text GEMM into g_ebuf (16 rows x 200 cols tile)
// Blocks [NG, NG+2*MB):  aggregation for 4 same-type batch elems -> g_vsh
__global__ __launch_bounds__(256) void kwork(
    const int*   __restrict__ indices,
    const float* __restrict__ text_features,
    const float* __restrict__ textT,     // [768,200]
    const int*   __restrict__ node_neigh,
    const float* __restrict__ neigh,     // [N,768]
    const float* __restrict__ tweetW,    // [2,768,20]
    const float* __restrict__ userW,     // [2,32,20]
    const float* __restrict__ S1,        // [2,20,20]
    const float* __restrict__ S2,        // [2,20,1]
    int NUv, int NG, int MB)
{
    __shared__ __align__(16) unsigned char smraw[sizeof(MainS) > sizeof(GemmS)
                                                 ? sizeof(MainS) : sizeof(GemmS)];
    const int tid = threadIdx.x;

    if (blockIdx.x < (unsigned)NG) {
        // ================= GEMM path =================
        GemmS& S = *reinterpret_cast<GemmS*>(smraw);
        const int ntext = g_ntext;
        const int base  = blockIdx.x * 16;
        if (base >= ntext) return;
        const int half = tid >> 7;
        const int ht   = tid & 127;

        if (tid < 16) {
            int p   = base + tid;
            int src = min(p, ntext - 1);
            int bb  = g_list[src];
            S.bls[tid] = (p < ntext) ? bb : -1;
            S.rws[tid] = indices[bb] - NUv;
        }
        __syncthreads();

        const int lbi = tid >> 4;
        const int lkk = (tid & 15) << 2;
        const float* xrow = text_features + (size_t)S.rws[lbi] * 768;

        *(float4*)&S.Xs[0][lbi][lkk] = *(const float4*)(xrow + lkk);
        __syncthreads();

        float acc[8][2];
#pragma unroll
        for (int i = 0; i < 8; ++i) { acc[i][0] = 0.f; acc[i][1] = 0.f; }

        const bool act = (ht < 100);
        const int  j0  = 2 * ht;
        const int  r0  = half * 8;

        for (int tile = 0; tile < 12; ++tile) {
            const int k0  = tile * 64;
            const int cur = tile & 1;
            if (tile < 11)
                *(float4*)&S.Xs[cur ^ 1][lbi][lkk] = *(const float4*)(xrow + k0 + 64 + lkk);
            if (act) {
#pragma unroll
                for (int kk = 0; kk < 64; kk += 4) {
                    float2 w0 = __ldg((const float2*)(textT + (size_t)(k0 + kk    ) * 200 + j0));
                    float2 w1 = __ldg((const float2*)(textT + (size_t)(k0 + kk + 1) * 200 + j0));
                    float2 w2 = __ldg((const float2*)(textT + (size_t)(k0 + kk + 2) * 200 + j0));
                    float2 w3 = __ldg((const float2*)(textT + (size_t)(k0 + kk + 3) * 200 + j0));
#pragma unroll
                    for (int bi = 0; bi < 8; ++bi) {
                        float4 x = *(const float4*)&S.Xs[cur][r0 + bi][kk];
                        acc[bi][0] = fmaf(x.x, w0.x, acc[bi][0]);
                        acc[bi][1] = fmaf(x.x, w0.y, acc[bi][1]);
                        acc[bi][0] = fmaf(x.y, w1.x, acc[bi][0]);
                        acc[bi][1] = fmaf(x.y, w1.y, acc[bi][1]);
                        acc[bi][0] = fmaf(x.z, w2.x, acc[bi][0]);
                        acc[bi][1] = fmaf(x.z, w2.y, acc[bi][1]);
                        acc[bi][0] = fmaf(x.w, w3.x, acc[bi][0]);
                        acc[bi][1] = fmaf(x.w, w3.y, acc[bi][1]);
                    }
                }
            }
            __syncthreads();
        }

        if (act) {
#pragma unroll
            for (int bi = 0; bi < 8; ++bi) {
                int bb = S.bls[r0 + bi];
                if (bb >= 0) {
                    float* d = g_ebuf + (size_t)bb * 200 + j0;
                    d[0] = acc[bi][0];
                    d[1] = acc[bi][1];
                }
            }
        }
        return;
    }

    // ================= aggregation path (4 same-type batch elems) =================
    MainS& S = *reinterpret_cast<MainS*>(smraw);
    const int j = blockIdx.x - NG;
    int bucket, pos, n;
    const int* ord;
    if (j < MB) { bucket = 1; pos = j * 4;        n = g_n1; ord = g_ord1; }
    else        { bucket = 0; pos = (j - MB) * 4; n = g_n0; ord = g_ord0; }
    if (pos >= n) return;
    const int nb = min(4, n - pos);

    if (tid < 80) {
        const int b  = tid / 20;
        const int s  = tid % 20;
        const int bb = ord[pos + min(b, nb - 1)];
        if (s == 0) S.bs[b] = bb;
        S.rows[b][s] = node_neigh[bb * 20 + s];
    }
    __syncthreads();

    const int K   = bucket ? 768 : 32;
    const int cpt = K >> 2;            // chunks per type slot: 192 or 8
    const int tpb = 2 * cpt;
    const int total = nb * tpb;

    // ---- Phase 1: neighbor-row sums ----
    for (int task = tid; task < total; task += 256) {
        const int b  = task / tpb;
        const int r  = task - b * tpb;
        const int t  = (r >= cpt) ? 1 : 0;
        const int cc = r - t * cpt;
        const int* rw = S.rows[b] + t * 10;
        float4 a = make_float4(0.f, 0.f, 0.f, 0.f);
#pragma unroll
        for (int s = 0; s < 10; ++s) {
            float4 v = __ldg((const float4*)(neigh + (size_t)rw[s] * 768 + 4 * cc));
            a.x += v.x; a.y += v.y; a.z += v.z; a.w += v.w;
        }
        *(float4*)&S.xs[b][t][4 * cc] = a;
    }
    __syncthreads();

    // ---- Phase 2: nte = xs . W, weights amortized across the 4 b's ----
    float a0[4], a1[4], a2[4], a3[4];
#pragma unroll
    for (int b = 0; b < 4; ++b) { a0[b] = a1[b] = a2[b] = a3[b] = 0.f; }
    const int kl   = tid / 10;
    const int slot = tid % 10;
    if (tid < 240) {
        const int t  = slot / 5;
        const int u0 = (slot % 5) * 4;
        const float* Wb = bucket ? (tweetW + (size_t)t * 768 * 20)
                                 : (userW  + (size_t)t * 32 * 20);
        for (int k = kl; k < K; k += 24) {
            float4 w = __ldg((const float4*)(Wb + k * 20 + u0));
#pragma unroll
            for (int b = 0; b < 4; ++b) {
                float x = S.xs[b][t][k];
                a0[b] = fmaf(x, w.x, a0[b]);
                a1[b] = fmaf(x, w.y, a1[b]);
                a2[b] = fmaf(x, w.z, a2[b]);
                a3[b] = fmaf(x, w.w, a3[b]);
            }
        }
    }
    __syncthreads();                       // all xs reads done; safe to overwrite
    float4* part = reinterpret_cast<float4*>(&S.xs[0][0][0]);   // [4][24][10]
    if (tid < 240) {
#pragma unroll
        for (int b = 0; b < 4; ++b)
            part[(b * 24 + kl) * 10 + slot] = make_float4(a0[b], a1[b], a2[b], a3[b]);
    }
    __syncthreads();
    if (tid < 160) {
        const int b = tid / 40, t = (tid % 40) / 20, u = tid % 20;
        const float* p = (const float*)(part + (b * 24) * 10 + t * 5 + (u >> 2)) + (u & 3);
        float s = 0.f;
#pragma unroll
        for (int k2 = 0; k2 < 24; ++k2) s += p[k2 * 40];
        S.nte[b][t][u] = s;
    }
    __syncthreads();

    // ---- Phase 3: attention ----
    if (tid < 160) {
        const int b = tid / 40, t = (tid % 40) / 20, aa = tid % 20;
        float h = 0.f;
#pragma unroll
        for (int u = 0; u < 20; ++u)
            h = fmaf(S.nte[b][t][u], S1[(bucket * 20 + u) * 20 + aa], h);
        S.sc[b][t * 20 + aa] = tanhf(h) * S2[bucket * 20 + aa];
    }
    __syncthreads();
    if (tid < 4) {
        const int b = tid;
        float s0 = 0.f, s1v = 0.f;
#pragma unroll
        for (int aa = 0; aa < 20; ++aa) { s0 += S.sc[b][aa]; s1v += S.sc[b][20 + aa]; }
        float m  = fmaxf(s0, s1v);
        float e0 = expf(s0 - m), e1 = expf(s1v - m);
        float iv = 1.f / (e0 + e1);
        S.att[b][0] = e0 * iv; S.att[b][1] = e1 * iv;
    }
    __syncthreads();
    if (tid < 80) {
        const int b = tid / 20, u = tid % 20;
        if (b < nb)
            g_vsh[(size_t)S.bs[b] * 20 + u] =
                S.att[b][0] * S.nte[b][0][u] + S.att[b][1] * S.nte[b][1][u];
    }
}

// ---------------- kernel 3: final combine + L2 normalize ----------------
__global__ __launch_bounds__(256) void kfin(
    const int*   __restrict__ train_types,
    const int*   __restrict__ indices,
    const float* __restrict__ user_features,
    const float* __restrict__ userT,    // [32,200]
    const float* __restrict__ TW,       // [2,20,200]
    float*       __restrict__ out,
    int NUv)
{
    const int b    = blockIdx.x;
    const int tid  = threadIdx.x;
    const int lane = tid & 31;
    const int wid  = tid >> 5;
    const int tau  = train_types[b];

    __shared__ float vsh[20];
    __shared__ float red[8];
    __shared__ float s_inv;

    if (tid < 20) vsh[tid] = g_vsh[(size_t)b * 20 + tid];
    __syncthreads();

    const int idx = indices[b];
    float o = 0.f;
    if (tid < 200) {
        if (idx >= NUv) {
            o = g_ebuf[(size_t)b * 200 + tid];
        } else {
            const float* uf = user_features + (size_t)idx * 32;
#pragma unroll
            for (int k = 0; k < 32; ++k) o = fmaf(uf[k], userT[k * 200 + tid], o);
        }
#pragma unroll
        for (int u = 0; u < 20; ++u) o = fmaf(vsh[u], TW[(tau * 20 + u) * 200 + tid], o);
    }
    float sq = o * o;
#pragma unroll
    for (int off = 16; off; off >>= 1) sq += __shfl_down_sync(0xffffffffu, sq, off);
    if (lane == 0) red[wid] = sq;
    __syncthreads();
    if (tid == 0) {
        float s = 0.f;
#pragma unroll
        for (int w = 0; w < 8; ++w) s += red[w];
        s_inv = 1.f / fmaxf(sqrtf(s), 1e-12f);
    }
    __syncthreads();
    if (tid < 200) out[(size_t)b * 200 + tid] = o * s_inv;
}

// ---------------- launch ----------------
extern "C" void kernel_launch(void* const* d_in, const int* in_sizes, int n_in,
                              void* d_out, int out_size)
{
    const int*   train_types    = (const int*)  d_in[1];
    const int*   node_neigh     = (const int*)  d_in[2];
    const int*   indices        = (const int*)  d_in[3];
    const float* user_features  = (const float*)d_in[4];
    const float* text_features  = (const float*)d_in[5];
    const float* neigh_features = (const float*)d_in[6];
    const float* textT          = (const float*)d_in[7];
    const float* userT          = (const float*)d_in[8];
    const float* tweetW         = (const float*)d_in[9];
    const float* userW          = (const float*)d_in[10];
    const float* TW             = (const float*)d_in[11];
    const float* S1             = (const float*)d_in[12];
    const float* S2             = (const float*)d_in[13];
    float*       out            = (float*)d_out;

    const int B   = in_sizes[1];          // 4096
    const int NUv = in_sizes[4] / 32;     // 50000
    const int NG  = (B + 15) / 16;        // worst-case GEMM tiles
    const int MB  = (B + 3) / 4;          // per-bucket aggregation blocks (upper bound)

    kzero<<<1, 1>>>();
    kpart<<<(B + 255) / 256, 256>>>(indices, train_types, B, NUv);
    kwork<<<NG + 2 * MB, 256>>>(indices, text_features, textT,
                                node_neigh, neigh_features,
                                tweetW, userW, S1, S2, NUv, NG, MB);
    kfin<<<B, 256>>>(train_types, indices, user_features, userT, TW, out, NUv);
}

// round 9
// speedup vs baseline: 1.4948x; 1.4948x over previous
#include <cuda_runtime.h>
#include <math.h>

// ---------------- device scratch (no allocation allowed) ----------------
static __device__ int   g_ntext;
static __device__ int   g_n1;
static __device__ int   g_n0;
static __device__ int   g_list[8192];
static __device__ int   g_ord1[8192];
static __device__ int   g_ord0[8192];
static __device__ float g_ebufA[8192 * 200];
static __device__ float g_ebufB[8192 * 200];
static __device__ float g_vsh[8192 * 20];

// ---------------- kernel 0: zero counters ----------------
__global__ void kzero() { g_ntext = 0; g_n1 = 0; g_n0 = 0; }

// ---------------- kernel 1: partition (text compaction + type buckets) --------
__global__ void kpart(const int* __restrict__ indices,
                      const int* __restrict__ types, int B, int NUv)
{
    int i = blockIdx.x * blockDim.x + threadIdx.x;
    if (i < B) {
        if (indices[i] >= NUv) g_list[atomicAdd(&g_ntext, 1)] = i;
        if (types[i] == 1) g_ord1[atomicAdd(&g_n1, 1)] = i;
        else               g_ord0[atomicAdd(&g_n0, 1)] = i;
    }
}

// ---------------- kernel 2: text base projection (gathered GEMM, K-split x2) ----
// Block (tile, h): 16 batch rows x 200 cols over k-range [h*384, h*384+384).
// 512 threads = 4 quarters of 128; quarter q owns rows q*4..q*4+3; threads
// 0..99 of each quarter own 2 cols. Partial sums -> g_ebufA / g_ebufB.
__global__ __launch_bounds__(512) void kgemm(const int* __restrict__ indices,
                                             const float* __restrict__ text_features,
                                             const float* __restrict__ textT,
                                             int NUv)
{
    const int ntext = g_ntext;
    const int tile  = blockIdx.x >> 1;
    const int h     = blockIdx.x & 1;
    const int base  = tile * 16;
    if (base >= ntext) return;
    const int tid = threadIdx.x;
    const int q   = tid >> 7;        // quarter 0..3
    const int ht  = tid & 127;

    __shared__ __align__(16) float Xs[2][16][68];
    __shared__ int bls[16];
    __shared__ int rws[16];

    if (tid < 16) {
        int p   = base + tid;
        int src = min(p, ntext - 1);
        int bb  = g_list[src];
        bls[tid] = (p < ntext) ? bb : -1;
        rws[tid] = indices[bb] - NUv;
    }
    __syncthreads();

    const int kbase = h * 384;

    // loader: threads 0..255, one float4 each (16 rows x 64 k)
    if (tid < 256) {
        const int lbi = tid >> 4;
        const int lkk = (tid & 15) << 2;
        *(float4*)&Xs[0][lbi][lkk] =
            *(const float4*)(text_features + (size_t)rws[lbi] * 768 + kbase + lkk);
    }
    __syncthreads();

    float acc[4][2];
#pragma unroll
    for (int i = 0; i < 4; ++i) { acc[i][0] = 0.f; acc[i][1] = 0.f; }

    const bool act = (ht < 100);
    const int  j0  = 2 * ht;
    const int  r0  = q * 4;

    for (int t = 0; t < 6; ++t) {
        const int k0  = kbase + t * 64;
        const int cur = t & 1;
        if (t < 5 && tid < 256) {
            const int lbi = tid >> 4;
            const int lkk = (tid & 15) << 2;
            *(float4*)&Xs[cur ^ 1][lbi][lkk] =
                *(const float4*)(text_features + (size_t)rws[lbi] * 768 + k0 + 64 + lkk);
        }
        if (act) {
#pragma unroll
            for (int kk = 0; kk < 64; kk += 4) {
                float2 w0 = __ldg((const float2*)(textT + (size_t)(k0 + kk    ) * 200 + j0));
                float2 w1 = __ldg((const float2*)(textT + (size_t)(k0 + kk + 1) * 200 + j0));
                float2 w2 = __ldg((const float2*)(textT + (size_t)(k0 + kk + 2) * 200 + j0));
                float2 w3 = __ldg((const float2*)(textT + (size_t)(k0 + kk + 3) * 200 + j0));
#pragma unroll
                for (int r = 0; r < 4; ++r) {
                    float4 x = *(const float4*)&Xs[cur][r0 + r][kk];
                    acc[r][0] = fmaf(x.x, w0.x, acc[r][0]);
                    acc[r][1] = fmaf(x.x, w0.y, acc[r][1]);
                    acc[r][0] = fmaf(x.y, w1.x, acc[r][0]);
                    acc[r][1] = fmaf(x.y, w1.y, acc[r][1]);
                    acc[r][0] = fmaf(x.z, w2.x, acc[r][0]);
                    acc[r][1] = fmaf(x.z, w2.y, acc[r][1]);
                    acc[r][0] = fmaf(x.w, w3.x, acc[r][0]);
                    acc[r][1] = fmaf(x.w, w3.y, acc[r][1]);
                }
            }
        }
        __syncthreads();
    }

    if (act) {
        float* ebuf = h ? g_ebufB : g_ebufA;
#pragma unroll
        for (int r = 0; r < 4; ++r) {
            int bb = bls[r0 + r];
            if (bb >= 0) {
                float* d = ebuf + (size_t)bb * 200 + j0;
                d[0] = acc[r][0];
                d[1] = acc[r][1];
            }
        }
    }
}

// ---------------- kernel 3: aggregation (4 same-type batch elems per block) -----
struct MainS {
    float xs[4][2][768];   // reused as float4 part[4][24][10] after phase 2
    int   rows[4][20];
    int   bs[4];
    float nte[4][2][20];
    float sc[4][40];
    float att[4][2];
};

__global__ __launch_bounds__(256) void kagg(
    const int*   __restrict__ node_neigh,
    const float* __restrict__ neigh,     // [N,768]
    const float* __restrict__ tweetW,    // [2,768,20]
    const float* __restrict__ userW,     // [2,32,20]
    const float* __restrict__ S1,        // [2,20,20]
    const float* __restrict__ S2,        // [2,20,1]
    int MB)
{
    __shared__ __align__(16) MainS S;
    const int tid = threadIdx.x;
    const int j = blockIdx.x;
    int bucket, pos, n;
    const int* ord;
    if (j < MB) { bucket = 1; pos = j * 4;        n = g_n1; ord = g_ord1; }
    else        { bucket = 0; pos = (j - MB) * 4; n = g_n0; ord = g_ord0; }
    if (pos >= n) return;
    const int nb = min(4, n - pos);

    if (tid < 80) {
        const int b  = tid / 20;
        const int s  = tid % 20;
        const int bb = ord[pos + min(b, nb - 1)];
        if (s == 0) S.bs[b] = bb;
        S.rows[b][s] = node_neigh[bb * 20 + s];
    }
    __syncthreads();

    const int K   = bucket ? 768 : 32;
    const int cpt = K >> 2;            // chunks per type slot: 192 or 8
    const int tpb = 2 * cpt;
    const int total = nb * tpb;

    // ---- Phase 1: neighbor-row sums ----
    for (int task = tid; task < total; task += 256) {
        const int b  = task / tpb;
        const int r  = task - b * tpb;
        const int t  = (r >= cpt) ? 1 : 0;
        const int cc = r - t * cpt;
        const int* rw = S.rows[b] + t * 10;
        float4 a = make_float4(0.f, 0.f, 0.f, 0.f);
#pragma unroll
        for (int s = 0; s < 10; ++s) {
            float4 v = __ldg((const float4*)(neigh + (size_t)rw[s] * 768 + 4 * cc));
            a.x += v.x; a.y += v.y; a.z += v.z; a.w += v.w;
        }
        *(float4*)&S.xs[b][t][4 * cc] = a;
    }
    __syncthreads();

    // ---- Phase 2: nte = xs . W, weights amortized across the 4 b's ----
    float a0[4], a1[4], a2[4], a3[4];
#pragma unroll
    for (int b = 0; b < 4; ++b) { a0[b] = a1[b] = a2[b] = a3[b] = 0.f; }
    const int kl   = tid / 10;
    const int slot = tid % 10;
    if (tid < 240) {
        const int t  = slot / 5;
        const int u0 = (slot % 5) * 4;
        const float* Wb = bucket ? (tweetW + (size_t)t * 768 * 20)
                                 : (userW  + (size_t)t * 32 * 20);
        for (int k = kl; k < K; k += 24) {
            float4 w = __ldg((const float4*)(Wb + k * 20 + u0));
#pragma unroll
            for (int b = 0; b < 4; ++b) {
                float x = S.xs[b][t][k];
                a0[b] = fmaf(x, w.x, a0[b]);
                a1[b] = fmaf(x, w.y, a1[b]);
                a2[b] = fmaf(x, w.z, a2[b]);
                a3[b] = fmaf(x, w.w, a3[b]);
            }
        }
    }
    __syncthreads();
    float4* part = reinterpret_cast<float4*>(&S.xs[0][0][0]);   // [4][24][10]
    if (tid < 240) {
#pragma unroll
        for (int b = 0; b < 4; ++b)
            part[(b * 24 + kl) * 10 + slot] = make_float4(a0[b], a1[b], a2[b], a3[b]);
    }
    __syncthreads();
    if (tid < 160) {
        const int b = tid / 40, t = (tid % 40) / 20, u = tid % 20;
        const float* p = (const float*)(part + (b * 24) * 10 + t * 5 + (u >> 2)) + (u & 3);
        float s = 0.f;
#pragma unroll
        for (int k2 = 0; k2 < 24; ++k2) s += p[k2 * 40];
        S.nte[b][t][u] = s;
    }
    __syncthreads();

    // ---- Phase 3: attention ----
    if (tid < 160) {
        const int b = tid / 40, t = (tid % 40) / 20, aa = tid % 20;
        float h = 0.f;
#pragma unroll
        for (int u = 0; u < 20; ++u)
            h = fmaf(S.nte[b][t][u], S1[(bucket * 20 + u) * 20 + aa], h);
        S.sc[b][t * 20 + aa] = tanhf(h) * S2[bucket * 20 + aa];
    }
    __syncthreads();
    if (tid < 4) {
        const int b = tid;
        float s0 = 0.f, s1v = 0.f;
#pragma unroll
        for (int aa = 0; aa < 20; ++aa) { s0 += S.sc[b][aa]; s1v += S.sc[b][20 + aa]; }
        float m  = fmaxf(s0, s1v);
        float e0 = expf(s0 - m), e1 = expf(s1v - m);
        float iv = 1.f / (e0 + e1);
        S.att[b][0] = e0 * iv; S.att[b][1] = e1 * iv;
    }
    __syncthreads();
    if (tid < 80) {
        const int b = tid / 20, u = tid % 20;
        if (b < nb)
            g_vsh[(size_t)S.bs[b] * 20 + u] =
                S.att[b][0] * S.nte[b][0][u] + S.att[b][1] * S.nte[b][1][u];
    }
}

// ---------------- kernel 4: final combine + L2 normalize (4 per block) ----------
__global__ __launch_bounds__(256) void kfin(
    const int*   __restrict__ indices,
    const float* __restrict__ user_features,
    const float* __restrict__ userT,    // [32,200]
    const float* __restrict__ TW,       // [2,20,200]
    float*       __restrict__ out,
    int NUv, int MB)
{
    const int tid  = threadIdx.x;
    const int lane = tid & 31;
    const int wid  = tid >> 5;
    const int j = blockIdx.x;
    int bucket, pos, n;
    const int* ord;
    if (j < MB) { bucket = 1; pos = j * 4;        n = g_n1; ord = g_ord1; }
    else        { bucket = 0; pos = (j - MB) * 4; n = g_n0; ord = g_ord0; }
    if (pos >= n) return;
    const int nb = min(4, n - pos);

    __shared__ __align__(16) float TWs[20 * 200];
    __shared__ __align__(16) float uTs[32 * 200];
    __shared__ float vshs[4][20];
    __shared__ int   bs[4];
    __shared__ int   idxs[4];
    __shared__ float red[4][8];
    __shared__ float sinv[4];

    // stage TW[bucket] (16 KB) into smem
    {
        const float4* src = (const float4*)(TW + (size_t)bucket * 20 * 200);
        float4* dst = (float4*)TWs;
        for (int i = tid; i < 1000; i += 256) dst[i] = src[i];
    }
    if (tid < 80) {
        const int b  = tid / 20;
        const int u  = tid % 20;
        const int bb = ord[pos + min(b, nb - 1)];
        if (u == 0) { bs[b] = bb; idxs[b] = indices[bb]; }
        vshs[b][u] = g_vsh[(size_t)bb * 20 + u];
    }
    __syncthreads();

    bool needU = false;
#pragma unroll
    for (int b = 0; b < 4; ++b) needU |= (idxs[b] < NUv);
    if (needU) {
        const float4* src = (const float4*)userT;
        float4* dst = (float4*)uTs;
        for (int i = tid; i < 1600; i += 256) dst[i] = src[i];
    }
    __syncthreads();

    float o[4];
#pragma unroll
    for (int b = 0; b < 4; ++b) {
        o[b] = 0.f;
        if (tid < 200) {
            const int idx = idxs[b];
            if (idx >= NUv) {
                o[b] = g_ebufA[(size_t)bs[b] * 200 + tid]
                     + g_ebufB[(size_t)bs[b] * 200 + tid];
            } else {
                const float* uf = user_features + (size_t)idx * 32;
#pragma unroll
                for (int k = 0; k < 32; ++k) o[b] = fmaf(uf[k], uTs[k * 200 + tid], o[b]);
            }
#pragma unroll
            for (int u = 0; u < 20; ++u) o[b] = fmaf(vshs[b][u], TWs[u * 200 + tid], o[b]);
        }
        float sq = o[b] * o[b];
#pragma unroll
        for (int off = 16; off; off >>= 1) sq += __shfl_down_sync(0xffffffffu, sq, off);
        if (lane == 0) red[b][wid] = sq;
    }
    __syncthreads();
    if (tid < 4) {
        float s = 0.f;
#pragma unroll
        for (int w = 0; w < 8; ++w) s += red[tid][w];
        sinv[tid] = 1.f / fmaxf(sqrtf(s), 1e-12f);
    }
    __syncthreads();
    if (tid < 200) {
        for (int b = 0; b < nb; ++b)
            out[(size_t)bs[b] * 200 + tid] = o[b] * sinv[b];
    }
}

// ---------------- launch ----------------
extern "C" void kernel_launch(void* const* d_in, const int* in_sizes, int n_in,
                              void* d_out, int out_size)
{
    const int*   train_types    = (const int*)  d_in[1];
    const int*   node_neigh     = (const int*)  d_in[2];
    const int*   indices        = (const int*)  d_in[3];
    const float* user_features  = (const float*)d_in[4];
    const float* text_features  = (const float*)d_in[5];
    const float* neigh_features = (const float*)d_in[6];
    const float* textT          = (const float*)d_in[7];
    const float* userT          = (const float*)d_in[8];
    const float* tweetW         = (const float*)d_in[9];
    const float* userW          = (const float*)d_in[10];
    const float* TW             = (const float*)d_in[11];
    const float* S1             = (const float*)d_in[12];
    const float* S2             = (const float*)d_in[13];
    float*       out            = (float*)d_out;

    const int B   = in_sizes[1];          // 4096
    const int NUv = in_sizes[4] / 32;     // 50000
    const int NT  = (B + 15) / 16;        // worst-case GEMM tiles
    const int MB  = (B + 3) / 4;          // per-bucket blocks (upper bound)

    kzero<<<1, 1>>>();
    kpart<<<(B + 255) / 256, 256>>>(indices, train_types, B, NUv);
    kgemm<<<2 * NT, 512>>>(indices, text_features, textT, NUv);
    kagg<<<2 * MB, 256>>>(node_neigh, neigh_features, tweetW, userW, S1, S2, MB);
    kfin<<<2 * MB, 256>>>(indices, user_features, userT, TW, out, NUv, MB);
}